// round 5
// baseline (speedup 1.0000x reference)
#include <cuda_runtime.h>
#include <math.h>

#define NN   200000
#define MM   12
#define FF   64
#define NBR  41
#define NBO  42           // padded outputs (w2[41]=0)
#define ORIG 92
#define BB   2000
#define SHH  9
#define NC   3
#define HF   128
#define NM   (NN*MM)
#define NPB  (NN/BB)      // 100 atoms per crystal
#define APB  128          // atoms per conv block
// edge kernel geometry
#define EPB2   256        // edges per block
#define NWARPE 7
#define NTHRE  (NWARPE*32)   // 224
#define ESTRIDE 264          // padded e-tile row stride (floats, 16B-aligned rows)
// folded: c0 * alpha * (1/M)
#define WSCALE (0.28209479177387814f * 0.125f / 12.0f)

typedef unsigned long long ull;

// scratch (allocation-free rule: __device__ globals)
__device__ float g_x[(size_t)NN * FF];       // 51.2 MB
__device__ float g_y[(size_t)NN * FF];       // 51.2 MB
__device__ float g_w[(size_t)NC * NM];       // 28.8 MB

__device__ __forceinline__ float softplusf(float t) {
    // fast + stable: max(t,0) + log(1 + exp(-|t|)); arg of log in (1,2]
    return fmaxf(t, 0.0f) + __logf(1.0f + __expf(-fabsf(t)));
}

// ---- packed fp32x2 helpers (SASS FFMA2; ptxas won't emit these itself) ----
__device__ __forceinline__ ull pack2(float lo, float hi) {
    ull r; asm("mov.b64 %0, {%1, %2};" : "=l"(r) : "f"(lo), "f"(hi)); return r;
}
__device__ __forceinline__ void unpack2(ull v, float& lo, float& hi) {
    asm("mov.b64 {%0, %1}, %2;" : "=f"(lo), "=f"(hi) : "l"(v));
}
__device__ __forceinline__ ull fma2(ull a, ull b, ull c) {
    ull d; asm("fma.rn.f32x2 %0, %1, %2, %3;" : "=l"(d) : "l"(a), "l"(b), "l"(c));
    return d;
}

// ---------------------------------------------------------------------------
// 1) x = atom_fea @ W_emb + b_emb      (200000 x 92) @ (92 x 64)
// ---------------------------------------------------------------------------
__global__ __launch_bounds__(256) void embed_kernel(
    const float* __restrict__ af, const float* __restrict__ W,
    const float* __restrict__ b)
{
    __shared__ float sW[ORIG][FF];
    __shared__ float sb[FF];
    for (int i = threadIdx.x; i < ORIG * FF; i += 256) sW[i >> 6][i & 63] = W[i];
    if (threadIdx.x < FF) sb[threadIdx.x] = b[threadIdx.x];
    __syncthreads();

    int a  = blockIdx.x * 16 + (threadIdx.x >> 4);
    int f0 = (threadIdx.x & 15) * 4;
    if (a >= NN) return;

    const float4* row4 = (const float4*)(af + (size_t)a * ORIG);
    ull acc0 = pack2(sb[f0], sb[f0 + 1]);
    ull acc1 = pack2(sb[f0 + 2], sb[f0 + 3]);
    #pragma unroll
    for (int k4 = 0; k4 < ORIG / 4; k4++) {
        float4 v = row4[k4];
        int k = k4 * 4;
        #pragma unroll
        for (int c = 0; c < 4; c++) {
            float vc = (c == 0) ? v.x : (c == 1) ? v.y : (c == 2) ? v.z : v.w;
            ull v2 = pack2(vc, vc);
            const ull* wr = (const ull*)&sW[k + c][f0];
            acc0 = fma2(v2, wr[0], acc0);
            acc1 = fma2(v2, wr[1], acc1);
        }
    }
    float4 o;
    unpack2(acc0, o.x, o.y);
    unpack2(acc1, o.z, o.w);
    *(float4*)&g_x[(size_t)a * FF + f0] = o;
}

// ---------------------------------------------------------------------------
// 2) Edge radial scalars — edge-pair f32x2 packing.
//    Block: 256 edges, 7 warps. Warp og = outputs og*6..og*6+5 (42 = 41 + pad).
//    Thread: 4 edge-pairs (edges lane*4..+3 and 128+lane*4..+3) x 6 outputs.
//    A-operand: two adjacent edges from transposed e-tile (LDS.128, no MOVs).
//    B-operand: weight pre-duplicated in smem (broadcast LDS.64, no MOVs).
//    Dynamic smem layout (bytes):
//      [0)      e_s  : 41*ESTRIDE floats      (43296)
//      [43296)  w1d  : 41*42 dup-pair ull     (13776)
//      [57072)  b1d  : 42 dup-pair ull        (  336)
//      [57408)  w2   : 42 float               (  168)
//      [57576)  b2   : 1 float (pad->57584)
//      [57584)  red  : 256*9 float            ( 9216)  total 66800
// ---------------------------------------------------------------------------
#define EOF_W1  43296
#define EOF_B1  57072
#define EOF_W2  57408
#define EOF_B2  57576
#define EOF_RED 57584
#define E_SMEM  66800

__global__ __launch_bounds__(NTHRE, 3) void edge_kernel(
    const float* __restrict__ nbr_fea,
    const float* __restrict__ Wr1, const float* __restrict__ br1,
    const float* __restrict__ Wr2, const float* __restrict__ br2)
{
    extern __shared__ char dsm[];
    float* e_s  = (float*)(dsm);
    ull*   w1d  = (ull*)  (dsm + EOF_W1);
    ull*   b1d  = (ull*)  (dsm + EOF_B1);
    float* w2_s = (float*)(dsm + EOF_W2);
    float* b2_s = (float*)(dsm + EOF_B2);
    float* red  = (float*)(dsm + EOF_RED);

    const int t    = threadIdx.x;
    const int og   = t >> 5;            // warp id: outputs og*6 .. og*6+5
    const int lane = t & 31;
    const int j0   = og * 6;
    const int leA  = lane * 4;          // edges leA..leA+3
    const int leB  = 128 + lane * 4;    // edges leB..leB+3
    const size_t base = (size_t)blockIdx.x * EPB2;

    // ---- stage e tile transposed (once; reused by all 3 layers) ----
    const float* eg_ptr = nbr_fea + base * NBR;
    for (int idx = t; idx < EPB2 * NBR; idx += NTHRE) {
        int le = idx / NBR;
        int k  = idx - le * NBR;
        e_s[k * ESTRIDE + le] = __ldg(&eg_ptr[idx]);
    }

    #pragma unroll 1
    for (int l = 0; l < NC; l++) {
        __syncthreads();   // e staged (l=0); prev layer fully done (l>0)

        // ---- load layer-l weights, duplicated into pair halves ----
        const float* W1l = Wr1 + (size_t)l * NBR * NBR;
        for (int idx = t; idx < NBR * NBO; idx += NTHRE) {
            int k = idx / NBO, j = idx - k * NBO;
            float w = (j < NBR) ? __ldg(&W1l[k * NBR + j]) : 0.f;
            w1d[idx] = pack2(w, w);
        }
        if (t < NBO) {
            float bv = (t < NBR) ? __ldg(&br1[l * NBR + t]) : 0.f;
            b1d[t] = pack2(bv, bv);
            w2_s[t] = (t < NBR) ? __ldg(&Wr2[((size_t)l * NBR + t) * SHH]) : 0.f;
        }
        if (t == 0) *b2_s = __ldg(&br2[l * SHH]);
        __syncthreads();

        // ---- k-loop: acc[pair p][output j], pair = (edge lo, edge hi) ----
        ull acc[4][6];
        #pragma unroll
        for (int j = 0; j < 6; j++) {
            ull bj = b1d[j0 + j];
            #pragma unroll
            for (int p = 0; p < 4; p++) acc[p][j] = bj;
        }

        #pragma unroll 2
        for (int k = 0; k < NBR; k++) {
            const float* erow = e_s + k * ESTRIDE;
            ulonglong2 ea = *(const ulonglong2*)(erow + leA);  // pairs (0,1),(2,3)
            ulonglong2 eb = *(const ulonglong2*)(erow + leB);  // pairs (4,5),(6,7)
            const ull* wrow = w1d + k * NBO + j0;
            #pragma unroll
            for (int j = 0; j < 6; j++) {
                ull bw = wrow[j];                              // broadcast LDS.64
                acc[0][j] = fma2(ea.x, bw, acc[0][j]);
                acc[1][j] = fma2(ea.y, bw, acc[1][j]);
                acc[2][j] = fma2(eb.x, bw, acc[2][j]);
                acc[3][j] = fma2(eb.y, bw, acc[3][j]);
            }
        }

        // ---- epilogue: per-edge partial sum_j softplus(.)*w2[j] ----
        float w2r[6];
        #pragma unroll
        for (int j = 0; j < 6; j++) w2r[j] = w2_s[j0 + j];

        #pragma unroll
        for (int p = 0; p < 4; p++) {
            float slo = 0.f, shi = 0.f;
            #pragma unroll
            for (int j = 0; j < 6; j++) {
                float lo, hi; unpack2(acc[p][j], lo, hi);
                slo += softplusf(lo) * w2r[j];
                shi += softplusf(hi) * w2r[j];
            }
            int e0 = (p < 2) ? (leA + 2 * p) : (leB + 2 * (p - 2));
            red[(e0    ) * 9 + og] = slo;
            red[(e0 + 1) * 9 + og] = shi;
        }
        __syncthreads();

        // ---- cross-warp reduce + store ----
        float b2v = *b2_s;
        for (int e = t; e < EPB2; e += NTHRE) {
            float s = b2v;
            #pragma unroll
            for (int o = 0; o < NWARPE; o++) s += red[e * 9 + o];
            g_w[(size_t)l * NM + base + e] = s * WSCALE;
        }
    }
}

// ---------------------------------------------------------------------------
// 3) Fused conv layer: y = weighted gather of xin, xout = y @ Wtp[l]
//    (exact round-2 code: known-good 124us/layer)
// ---------------------------------------------------------------------------
__global__ __launch_bounds__(256) void conv_kernel(
    const int* __restrict__ nbr_idx, const float* __restrict__ Wtp_l,
    const float* __restrict__ wl,
    const float* __restrict__ xin, float* __restrict__ xout)
{
    __shared__ float y_s[APB][68];
    __shared__ float sW[FF][FF];

    int t = threadIdx.x;
    for (int i = t; i < FF * FF; i += 256) sW[i >> 6][i & 63] = Wtp_l[i];

    int base = blockIdx.x * APB;
    int fg = t & 7;
    int f0 = fg * 8;

    #pragma unroll 1
    for (int r = 0; r < 4; r++) {
        int la = (t >> 3) + r * 32;
        int a  = base + la;
        float4 a0 = make_float4(0.f, 0.f, 0.f, 0.f);
        float4 a1 = make_float4(0.f, 0.f, 0.f, 0.f);
        if (a < NN) {
            #pragma unroll
            for (int j = 0; j < MM; j++) {
                int   s  = __ldg(&nbr_idx[a * MM + j]);
                float wj = __ldg(&wl[a * MM + j]);
                const float4* xr = (const float4*)(xin + (size_t)s * FF + f0);
                float4 v0 = __ldg(&xr[0]);
                float4 v1 = __ldg(&xr[1]);
                a0.x += wj * v0.x; a0.y += wj * v0.y; a0.z += wj * v0.z; a0.w += wj * v0.w;
                a1.x += wj * v1.x; a1.y += wj * v1.y; a1.z += wj * v1.z; a1.w += wj * v1.w;
            }
        }
        *(float4*)&y_s[la][f0]     = a0;
        *(float4*)&y_s[la][f0 + 4] = a1;
    }
    __syncthreads();

    int la0 = (t >> 3) * 4;
    ull acc[4][4];
    #pragma unroll
    for (int i = 0; i < 4; i++)
        #pragma unroll
        for (int p = 0; p < 4; p++) acc[i][p] = 0ULL;

    #pragma unroll 4
    for (int k4 = 0; k4 < FF / 4; k4++) {
        float4 yv[4];
        #pragma unroll
        for (int i = 0; i < 4; i++) yv[i] = *(const float4*)&y_s[la0 + i][k4 * 4];
        #pragma unroll
        for (int c = 0; c < 4; c++) {
            int k = k4 * 4 + c;
            ulonglong2 wa = *(const ulonglong2*)&sW[k][f0];
            ulonglong2 wb = *(const ulonglong2*)&sW[k][f0 + 4];
            #pragma unroll
            for (int i = 0; i < 4; i++) {
                float yc = (c == 0) ? yv[i].x : (c == 1) ? yv[i].y : (c == 2) ? yv[i].z : yv[i].w;
                ull y2 = pack2(yc, yc);
                acc[i][0] = fma2(y2, wa.x, acc[i][0]);
                acc[i][1] = fma2(y2, wa.y, acc[i][1]);
                acc[i][2] = fma2(y2, wb.x, acc[i][2]);
                acc[i][3] = fma2(y2, wb.y, acc[i][3]);
            }
        }
    }

    #pragma unroll
    for (int i = 0; i < 4; i++) {
        int a = base + la0 + i;
        if (a >= NN) break;
        float4 o0, o1;
        unpack2(acc[i][0], o0.x, o0.y);
        unpack2(acc[i][1], o0.z, o0.w);
        unpack2(acc[i][2], o1.x, o1.y);
        unpack2(acc[i][3], o1.z, o1.w);
        float* xo = xout + (size_t)a * FF + f0;
        *(float4*)(xo)     = o0;
        *(float4*)(xo + 4) = o1;
    }
}

// ---------------------------------------------------------------------------
// 4) crystal pooling + fc + out. One block (128 thr) per crystal.
// ---------------------------------------------------------------------------
__global__ __launch_bounds__(128) void pool_kernel(
    const float* __restrict__ xin,
    const int* __restrict__ cidx,
    const float* __restrict__ Wfc, const float* __restrict__ bfc,
    const float* __restrict__ Wout, const float* __restrict__ bout,
    float* __restrict__ out, float* __restrict__ hout)
{
    __shared__ float scrys[FF];
    __shared__ float sred[HF];
    int b    = blockIdx.x;
    int tid  = threadIdx.x;
    int f    = tid & 63;
    int half = tid >> 6;

    float acc = 0.f;
    for (int a = half * (NPB / 2); a < (half + 1) * (NPB / 2); a++) {
        int atom = __ldg(&cidx[b * NPB + a]);
        acc += xin[(size_t)atom * FF + f];
    }
    if (half == 1) scrys[f] = acc;
    __syncthreads();
    if (half == 0) scrys[f] = (scrys[f] + acc) * (1.0f / NPB);
    __syncthreads();

    float hv = bfc[tid];
    #pragma unroll
    for (int k = 0; k < FF; k++) hv += scrys[k] * Wfc[k * HF + tid];
    hv = fmaxf(hv, 0.0f) + log1pf(__expf(-fabsf(hv)));   // precise softplus here
    if (hout) hout[(size_t)b * HF + tid] = hv;

    sred[tid] = hv * Wout[tid];
    __syncthreads();
    #pragma unroll
    for (int s = 64; s > 0; s >>= 1) {
        if (tid < s) sred[tid] += sred[tid + s];
        __syncthreads();
    }
    if (tid == 0) out[b] = sred[0] + bout[0];
}

// ---------------------------------------------------------------------------
extern "C" void kernel_launch(void* const* d_in, const int* in_sizes, int n_in,
                              void* d_out, int out_size)
{
    const float* atom_fea = (const float*)d_in[0];
    const float* nbr_fea  = (const float*)d_in[1];
    const int*   nbr_idx  = (const int*)  d_in[2];
    const int*   cidx     = (const int*)  d_in[3];
    // d_in[4] = pos : unused (Y0 is a constant)
    const float* W_emb = (const float*)d_in[5];
    const float* b_emb = (const float*)d_in[6];
    const float* Wr1   = (const float*)d_in[7];
    const float* br1   = (const float*)d_in[8];
    const float* Wr2   = (const float*)d_in[9];
    const float* br2   = (const float*)d_in[10];
    const float* Wtp   = (const float*)d_in[11];
    const float* W_fc  = (const float*)d_in[12];
    const float* b_fc  = (const float*)d_in[13];
    const float* W_out = (const float*)d_in[14];
    const float* b_out = (const float*)d_in[15];

    float* out_f = (float*)d_out;
    float* h_f   = (out_size >= BB + BB * HF) ? out_f + BB : nullptr;

    float* gx; cudaGetSymbolAddress((void**)&gx, g_x);
    float* gy; cudaGetSymbolAddress((void**)&gy, g_y);
    float* gw; cudaGetSymbolAddress((void**)&gw, g_w);

    static int smem_set = 0;
    if (!smem_set) {
        cudaFuncSetAttribute(edge_kernel,
                             cudaFuncAttributeMaxDynamicSharedMemorySize, E_SMEM);
        smem_set = 1;
    }

    embed_kernel<<<(NN + 15) / 16, 256>>>(atom_fea, W_emb, b_emb);
    edge_kernel<<<NM / EPB2, NTHRE, E_SMEM>>>(nbr_fea, Wr1, br1, Wr2, br2);

    // layer ping-pong: x -> y -> x -> y
    conv_kernel<<<(NN + APB - 1) / APB, 256>>>(nbr_idx, Wtp + 0 * FF * FF, gw + 0 * (size_t)NM, gx, gy);
    conv_kernel<<<(NN + APB - 1) / APB, 256>>>(nbr_idx, Wtp + 1 * FF * FF, gw + 1 * (size_t)NM, gy, gx);
    conv_kernel<<<(NN + APB - 1) / APB, 256>>>(nbr_idx, Wtp + 2 * FF * FF, gw + 2 * (size_t)NM, gx, gy);

    pool_kernel<<<BB, 128>>>(gy, cidx, W_fc, b_fc, W_out, b_out, out_f, h_f);
}

// round 6
// speedup vs baseline: 1.1385x; 1.1385x over previous
#include <cuda_runtime.h>
#include <math.h>

#define NN   200000
#define MM   12
#define FF   64
#define NBR  41
#define NPAIRS 21         // 42 padded outputs = 21 f32x2 pairs (pad col 41 = 0)
#define ORIG 92
#define BB   2000
#define SHH  9
#define NC   3
#define HF   128
#define NM   (NN*MM)
#define NPB  (NN/BB)      // 100 atoms per crystal
#define APB  128          // atoms per conv block
// edge kernel geometry
#define EPB2   256        // edges per block
#define NWARPE 7
#define NTHRE  (NWARPE*32)   // 224
#define ESTRIDE 264          // padded e-tile row stride (floats, 16B-aligned rows)
// folded: c0 * alpha * (1/M)
#define WSCALE (0.28209479177387814f * 0.125f / 12.0f)

typedef unsigned long long ull;

// scratch (allocation-free rule: __device__ globals)
__device__ float g_x[(size_t)NN * FF];       // 51.2 MB
__device__ float g_y[(size_t)NN * FF];       // 51.2 MB
__device__ float g_w[(size_t)NC * NM];       // 28.8 MB

__device__ __forceinline__ float softplusf(float t) {
    // fast + stable: max(t,0) + log(1 + exp(-|t|)); arg of log in (1,2]
    return fmaxf(t, 0.0f) + __logf(1.0f + __expf(-fabsf(t)));
}

// ---- packed fp32x2 helpers (SASS FFMA2; ptxas won't emit these itself) ----
__device__ __forceinline__ ull pack2(float lo, float hi) {
    ull r; asm("mov.b64 %0, {%1, %2};" : "=l"(r) : "f"(lo), "f"(hi)); return r;
}
__device__ __forceinline__ void unpack2(ull v, float& lo, float& hi) {
    asm("mov.b64 {%0, %1}, %2;" : "=f"(lo), "=f"(hi) : "l"(v));
}
__device__ __forceinline__ ull fma2(ull a, ull b, ull c) {
    ull d; asm("fma.rn.f32x2 %0, %1, %2, %3;" : "=l"(d) : "l"(a), "l"(b), "l"(c));
    return d;
}

// ---------------------------------------------------------------------------
// 1) x = atom_fea @ W_emb + b_emb      (200000 x 92) @ (92 x 64)
// ---------------------------------------------------------------------------
__global__ __launch_bounds__(256) void embed_kernel(
    const float* __restrict__ af, const float* __restrict__ W,
    const float* __restrict__ b)
{
    __shared__ float sW[ORIG][FF];
    __shared__ float sb[FF];
    for (int i = threadIdx.x; i < ORIG * FF; i += 256) sW[i >> 6][i & 63] = W[i];
    if (threadIdx.x < FF) sb[threadIdx.x] = b[threadIdx.x];
    __syncthreads();

    int a  = blockIdx.x * 16 + (threadIdx.x >> 4);
    int f0 = (threadIdx.x & 15) * 4;
    if (a >= NN) return;

    const float4* row4 = (const float4*)(af + (size_t)a * ORIG);
    ull acc0 = pack2(sb[f0], sb[f0 + 1]);
    ull acc1 = pack2(sb[f0 + 2], sb[f0 + 3]);
    #pragma unroll
    for (int k4 = 0; k4 < ORIG / 4; k4++) {
        float4 v = row4[k4];
        int k = k4 * 4;
        #pragma unroll
        for (int c = 0; c < 4; c++) {
            float vc = (c == 0) ? v.x : (c == 1) ? v.y : (c == 2) ? v.z : v.w;
            ull v2 = pack2(vc, vc);
            const ull* wr = (const ull*)&sW[k + c][f0];
            acc0 = fma2(v2, wr[0], acc0);
            acc1 = fma2(v2, wr[1], acc1);
        }
    }
    float4 o;
    unpack2(acc0, o.x, o.y);
    unpack2(acc1, o.z, o.w);
    *(float4*)&g_x[(size_t)a * FF + f0] = o;
}

// ---------------------------------------------------------------------------
// 2) Edge radial scalars (R4 structure, contiguous A-loads).
//    Block: 256 edges, 7 warps. Warp = 3 output pairs (21 pairs = 42 = 41+pad).
//    Thread = 8 edges (leA..leA+3, leB..leB+3) x 3 pairs.
//    A: two contiguous-512B LDS.128 per k (4 wavefronts each).
//    B: 3 broadcast LDS.64 per k (pair-packed outputs).
//    Dynamic smem layout (bytes):
//      [0)        e_s   : 41 * ESTRIDE floats          (43296)
//      [43296)    w1_s  : 41 * 21 ull pairs            ( 6888)
//      [50184)    b1_s  : 21 ull                       (  168)
//      [50352)    w2_s  : 42 float                     (  168)
//      [50520)    b2_s  : 1 float (+pad to 50528)
//      [50528)    red   : 256 * 9 floats               ( 9216)   total 59744
// ---------------------------------------------------------------------------
#define EOF_W1  43296
#define EOF_B1  50184
#define EOF_W2  50352
#define EOF_B2  50520
#define EOF_RED 50528
#define E_SMEM  59744

__global__ __launch_bounds__(NTHRE, 3) void edge_kernel(
    const float* __restrict__ nbr_fea,
    const float* __restrict__ Wr1, const float* __restrict__ br1,
    const float* __restrict__ Wr2, const float* __restrict__ br2)
{
    extern __shared__ char dsm[];
    float* e_s  = (float*)(dsm);
    ull*   w1_s = (ull*)  (dsm + EOF_W1);
    ull*   b1_s = (ull*)  (dsm + EOF_B1);
    float* w2_s = (float*)(dsm + EOF_W2);
    float* b2_s = (float*)(dsm + EOF_B2);
    float* red  = (float*)(dsm + EOF_RED);

    const int t    = threadIdx.x;
    const int og   = t >> 5;            // warp id: pairs og*3 .. og*3+2
    const int lane = t & 31;
    const int p0   = og * 3;
    const int leA  = lane * 4;          // edges leA..leA+3 (contiguous per warp)
    const int leB  = 128 + lane * 4;    // edges leB..leB+3
    const size_t base = (size_t)blockIdx.x * EPB2;

    // ---- stage e tile transposed (once; reused by all 3 layers) ----
    const float* eg_ptr = nbr_fea + base * NBR;
    for (int idx = t; idx < EPB2 * NBR; idx += NTHRE) {
        int le = idx / NBR;
        int k  = idx - le * NBR;
        e_s[k * ESTRIDE + le] = __ldg(&eg_ptr[idx]);
    }

    #pragma unroll 1
    for (int l = 0; l < NC; l++) {
        __syncthreads();   // e staged (l=0); prev layer fully done (l>0)

        // ---- load layer-l weights (output pairs, j/j+1 packed) ----
        const float* W1l = Wr1 + (size_t)l * NBR * NBR;
        for (int idx = t; idx < NBR * NPAIRS; idx += NTHRE) {
            int k = idx / NPAIRS, j = idx - k * NPAIRS;
            int j2 = 2 * j;
            float lo = __ldg(&W1l[k * NBR + j2]);
            float hi = (j2 + 1 < NBR) ? __ldg(&W1l[k * NBR + j2 + 1]) : 0.f;
            w1_s[k * NPAIRS + j] = pack2(lo, hi);
        }
        if (t < NPAIRS) {
            int j2 = 2 * t;
            float lo = __ldg(&br1[l * NBR + j2]);
            float hi = (j2 + 1 < NBR) ? __ldg(&br1[l * NBR + j2 + 1]) : 0.f;
            b1_s[t] = pack2(lo, hi);
        }
        if (t < 2 * NPAIRS)
            w2_s[t] = (t < NBR) ? __ldg(&Wr2[((size_t)l * NBR + t) * SHH]) : 0.f;
        if (t == 0) *b2_s = __ldg(&br2[l * SHH]);
        __syncthreads();

        // ---- k-loop: acc[edge 0..7][pair 0..2] ----
        ull acc[8][3];
        {
            ull b0 = b1_s[p0], b1 = b1_s[p0 + 1], b2 = b1_s[p0 + 2];
            #pragma unroll
            for (int i = 0; i < 8; i++) { acc[i][0] = b0; acc[i][1] = b1; acc[i][2] = b2; }
        }

        #pragma unroll 2
        for (int k = 0; k < NBR; k++) {
            const float* erow = e_s + k * ESTRIDE;
            float4 a0 = *(const float4*)(erow + leA);   // contiguous 512B / warp
            float4 a1 = *(const float4*)(erow + leB);   // contiguous 512B / warp
            ull bw0 = w1_s[k * NPAIRS + p0];
            ull bw1 = w1_s[k * NPAIRS + p0 + 1];
            ull bw2 = w1_s[k * NPAIRS + p0 + 2];
            float ev[8] = {a0.x, a0.y, a0.z, a0.w, a1.x, a1.y, a1.z, a1.w};
            #pragma unroll
            for (int i = 0; i < 8; i++) {
                ull a2 = pack2(ev[i], ev[i]);
                acc[i][0] = fma2(a2, bw0, acc[i][0]);
                acc[i][1] = fma2(a2, bw1, acc[i][1]);
                acc[i][2] = fma2(a2, bw2, acc[i][2]);
            }
        }

        // ---- epilogue: softplus . w2 partials into red ----
        float w2a = w2_s[p0 * 2],     w2b = w2_s[p0 * 2 + 1];
        float w2c = w2_s[p0 * 2 + 2], w2d = w2_s[p0 * 2 + 3];
        float w2e = w2_s[p0 * 2 + 4], w2f = w2_s[p0 * 2 + 5];
        #pragma unroll
        for (int i = 0; i < 8; i++) {
            float lo, hi, s;
            unpack2(acc[i][0], lo, hi);
            s  = softplusf(lo) * w2a + softplusf(hi) * w2b;
            unpack2(acc[i][1], lo, hi);
            s += softplusf(lo) * w2c + softplusf(hi) * w2d;
            unpack2(acc[i][2], lo, hi);
            s += softplusf(lo) * w2e + softplusf(hi) * w2f;
            int el = (i < 4) ? (leA + i) : (leB + i - 4);
            red[el * 9 + og] = s;
        }
        __syncthreads();

        // ---- cross-warp reduce + store ----
        float b2v = *b2_s;
        for (int e = t; e < EPB2; e += NTHRE) {
            float s = b2v;
            #pragma unroll
            for (int o = 0; o < NWARPE; o++) s += red[e * 9 + o];
            g_w[(size_t)l * NM + base + e] = s * WSCALE;
        }
    }
}

// ---------------------------------------------------------------------------
// 3) Fused conv layer: y = weighted gather of xin, xout = y @ Wtp[l]
//    (exact round-2 code: known-good 124us/layer)
// ---------------------------------------------------------------------------
__global__ __launch_bounds__(256) void conv_kernel(
    const int* __restrict__ nbr_idx, const float* __restrict__ Wtp_l,
    const float* __restrict__ wl,
    const float* __restrict__ xin, float* __restrict__ xout)
{
    __shared__ float y_s[APB][68];
    __shared__ float sW[FF][FF];

    int t = threadIdx.x;
    for (int i = t; i < FF * FF; i += 256) sW[i >> 6][i & 63] = Wtp_l[i];

    int base = blockIdx.x * APB;
    int fg = t & 7;
    int f0 = fg * 8;

    #pragma unroll 1
    for (int r = 0; r < 4; r++) {
        int la = (t >> 3) + r * 32;
        int a  = base + la;
        float4 a0 = make_float4(0.f, 0.f, 0.f, 0.f);
        float4 a1 = make_float4(0.f, 0.f, 0.f, 0.f);
        if (a < NN) {
            #pragma unroll
            for (int j = 0; j < MM; j++) {
                int   s  = __ldg(&nbr_idx[a * MM + j]);
                float wj = __ldg(&wl[a * MM + j]);
                const float4* xr = (const float4*)(xin + (size_t)s * FF + f0);
                float4 v0 = __ldg(&xr[0]);
                float4 v1 = __ldg(&xr[1]);
                a0.x += wj * v0.x; a0.y += wj * v0.y; a0.z += wj * v0.z; a0.w += wj * v0.w;
                a1.x += wj * v1.x; a1.y += wj * v1.y; a1.z += wj * v1.z; a1.w += wj * v1.w;
            }
        }
        *(float4*)&y_s[la][f0]     = a0;
        *(float4*)&y_s[la][f0 + 4] = a1;
    }
    __syncthreads();

    int la0 = (t >> 3) * 4;
    ull acc[4][4];
    #pragma unroll
    for (int i = 0; i < 4; i++)
        #pragma unroll
        for (int p = 0; p < 4; p++) acc[i][p] = 0ULL;

    #pragma unroll 4
    for (int k4 = 0; k4 < FF / 4; k4++) {
        float4 yv[4];
        #pragma unroll
        for (int i = 0; i < 4; i++) yv[i] = *(const float4*)&y_s[la0 + i][k4 * 4];
        #pragma unroll
        for (int c = 0; c < 4; c++) {
            int k = k4 * 4 + c;
            ulonglong2 wa = *(const ulonglong2*)&sW[k][f0];
            ulonglong2 wb = *(const ulonglong2*)&sW[k][f0 + 4];
            #pragma unroll
            for (int i = 0; i < 4; i++) {
                float yc = (c == 0) ? yv[i].x : (c == 1) ? yv[i].y : (c == 2) ? yv[i].z : yv[i].w;
                ull y2 = pack2(yc, yc);
                acc[i][0] = fma2(y2, wa.x, acc[i][0]);
                acc[i][1] = fma2(y2, wa.y, acc[i][1]);
                acc[i][2] = fma2(y2, wb.x, acc[i][2]);
                acc[i][3] = fma2(y2, wb.y, acc[i][3]);
            }
        }
    }

    #pragma unroll
    for (int i = 0; i < 4; i++) {
        int a = base + la0 + i;
        if (a >= NN) break;
        float4 o0, o1;
        unpack2(acc[i][0], o0.x, o0.y);
        unpack2(acc[i][1], o0.z, o0.w);
        unpack2(acc[i][2], o1.x, o1.y);
        unpack2(acc[i][3], o1.z, o1.w);
        float* xo = xout + (size_t)a * FF + f0;
        *(float4*)(xo)     = o0;
        *(float4*)(xo + 4) = o1;
    }
}

// ---------------------------------------------------------------------------
// 4) crystal pooling + fc + out. One block (128 thr) per crystal.
// ---------------------------------------------------------------------------
__global__ __launch_bounds__(128) void pool_kernel(
    const float* __restrict__ xin,
    const int* __restrict__ cidx,
    const float* __restrict__ Wfc, const float* __restrict__ bfc,
    const float* __restrict__ Wout, const float* __restrict__ bout,
    float* __restrict__ out, float* __restrict__ hout)
{
    __shared__ float scrys[FF];
    __shared__ float sred[HF];
    int b    = blockIdx.x;
    int tid  = threadIdx.x;
    int f    = tid & 63;
    int half = tid >> 6;

    float acc = 0.f;
    for (int a = half * (NPB / 2); a < (half + 1) * (NPB / 2); a++) {
        int atom = __ldg(&cidx[b * NPB + a]);
        acc += xin[(size_t)atom * FF + f];
    }
    if (half == 1) scrys[f] = acc;
    __syncthreads();
    if (half == 0) scrys[f] = (scrys[f] + acc) * (1.0f / NPB);
    __syncthreads();

    float hv = bfc[tid];
    #pragma unroll
    for (int k = 0; k < FF; k++) hv += scrys[k] * Wfc[k * HF + tid];
    hv = fmaxf(hv, 0.0f) + log1pf(__expf(-fabsf(hv)));   // precise softplus here
    if (hout) hout[(size_t)b * HF + tid] = hv;

    sred[tid] = hv * Wout[tid];
    __syncthreads();
    #pragma unroll
    for (int s = 64; s > 0; s >>= 1) {
        if (tid < s) sred[tid] += sred[tid + s];
        __syncthreads();
    }
    if (tid == 0) out[b] = sred[0] + bout[0];
}

// ---------------------------------------------------------------------------
extern "C" void kernel_launch(void* const* d_in, const int* in_sizes, int n_in,
                              void* d_out, int out_size)
{
    const float* atom_fea = (const float*)d_in[0];
    const float* nbr_fea  = (const float*)d_in[1];
    const int*   nbr_idx  = (const int*)  d_in[2];
    const int*   cidx     = (const int*)  d_in[3];
    // d_in[4] = pos : unused (Y0 is a constant)
    const float* W_emb = (const float*)d_in[5];
    const float* b_emb = (const float*)d_in[6];
    const float* Wr1   = (const float*)d_in[7];
    const float* br1   = (const float*)d_in[8];
    const float* Wr2   = (const float*)d_in[9];
    const float* br2   = (const float*)d_in[10];
    const float* Wtp   = (const float*)d_in[11];
    const float* W_fc  = (const float*)d_in[12];
    const float* b_fc  = (const float*)d_in[13];
    const float* W_out = (const float*)d_in[14];
    const float* b_out = (const float*)d_in[15];

    float* out_f = (float*)d_out;
    float* h_f   = (out_size >= BB + BB * HF) ? out_f + BB : nullptr;

    float* gx; cudaGetSymbolAddress((void**)&gx, g_x);
    float* gy; cudaGetSymbolAddress((void**)&gy, g_y);
    float* gw; cudaGetSymbolAddress((void**)&gw, g_w);

    static int smem_set = 0;
    if (!smem_set) {
        cudaFuncSetAttribute(edge_kernel,
                             cudaFuncAttributeMaxDynamicSharedMemorySize, E_SMEM);
        smem_set = 1;
    }

    embed_kernel<<<(NN + 15) / 16, 256>>>(atom_fea, W_emb, b_emb);
    edge_kernel<<<NM / EPB2, NTHRE, E_SMEM>>>(nbr_fea, Wr1, br1, Wr2, br2);

    // layer ping-pong: x -> y -> x -> y
    conv_kernel<<<(NN + APB - 1) / APB, 256>>>(nbr_idx, Wtp + 0 * FF * FF, gw + 0 * (size_t)NM, gx, gy);
    conv_kernel<<<(NN + APB - 1) / APB, 256>>>(nbr_idx, Wtp + 1 * FF * FF, gw + 1 * (size_t)NM, gy, gx);
    conv_kernel<<<(NN + APB - 1) / APB, 256>>>(nbr_idx, Wtp + 2 * FF * FF, gw + 2 * (size_t)NM, gx, gy);

    pool_kernel<<<BB, 128>>>(gy, cidx, W_fc, b_fc, W_out, b_out, out_f, h_f);
}

// round 7
// speedup vs baseline: 1.1661x; 1.0242x over previous
#include <cuda_runtime.h>
#include <math.h>

#define NN   200000
#define MM   12
#define FF   64
#define NBR  41
#define NPAIRS 21         // 42 padded outputs = 21 f32x2 pairs (pad col 41 = 0)
#define ORIG 92
#define BB   2000
#define SHH  9
#define NC   3
#define HF   128
#define NM   (NN*MM)
#define NPB  (NN/BB)      // 100 atoms per crystal
#define APB  128          // atoms per conv block
// edge kernel geometry
#define EPB2   256        // edges per block
#define NWARPE 7
#define NTHRE  (NWARPE*32)   // 224
#define ESTRIDE 264          // padded e-tile row stride (floats, 16B-aligned rows)
// folded: c0 * alpha * (1/M)
#define WSCALE (0.28209479177387814f * 0.125f / 12.0f)

typedef unsigned long long ull;

// scratch (allocation-free rule: __device__ globals)
__device__ float g_x[(size_t)NN * FF];       // 51.2 MB
__device__ float g_y[(size_t)NN * FF];       // 51.2 MB
__device__ float g_w[(size_t)NC * NM];       // 28.8 MB

__device__ __forceinline__ float softplusf(float t) {
    // fast + stable: max(t,0) + log(1 + exp(-|t|)); arg of log in (1,2]
    return fmaxf(t, 0.0f) + __logf(1.0f + __expf(-fabsf(t)));
}

// ---- packed fp32x2 helpers (SASS FFMA2; ptxas won't emit these itself) ----
__device__ __forceinline__ ull pack2(float lo, float hi) {
    ull r; asm("mov.b64 %0, {%1, %2};" : "=l"(r) : "f"(lo), "f"(hi)); return r;
}
__device__ __forceinline__ void unpack2(ull v, float& lo, float& hi) {
    asm("mov.b64 {%0, %1}, %2;" : "=f"(lo), "=f"(hi) : "l"(v));
}
__device__ __forceinline__ ull fma2(ull a, ull b, ull c) {
    ull d; asm("fma.rn.f32x2 %0, %1, %2, %3;" : "=l"(d) : "l"(a), "l"(b), "l"(c));
    return d;
}

// ---------------------------------------------------------------------------
// 1) x = atom_fea @ W_emb + b_emb      (200000 x 92) @ (92 x 64)
// ---------------------------------------------------------------------------
__global__ __launch_bounds__(256) void embed_kernel(
    const float* __restrict__ af, const float* __restrict__ W,
    const float* __restrict__ b)
{
    __shared__ float sW[ORIG][FF];
    __shared__ float sb[FF];
    for (int i = threadIdx.x; i < ORIG * FF; i += 256) sW[i >> 6][i & 63] = W[i];
    if (threadIdx.x < FF) sb[threadIdx.x] = b[threadIdx.x];
    __syncthreads();

    int a  = blockIdx.x * 16 + (threadIdx.x >> 4);
    int f0 = (threadIdx.x & 15) * 4;
    if (a >= NN) return;

    const float4* row4 = (const float4*)(af + (size_t)a * ORIG);
    ull acc0 = pack2(sb[f0], sb[f0 + 1]);
    ull acc1 = pack2(sb[f0 + 2], sb[f0 + 3]);
    #pragma unroll
    for (int k4 = 0; k4 < ORIG / 4; k4++) {
        float4 v = row4[k4];
        int k = k4 * 4;
        #pragma unroll
        for (int c = 0; c < 4; c++) {
            float vc = (c == 0) ? v.x : (c == 1) ? v.y : (c == 2) ? v.z : v.w;
            ull v2 = pack2(vc, vc);
            const ull* wr = (const ull*)&sW[k + c][f0];
            acc0 = fma2(v2, wr[0], acc0);
            acc1 = fma2(v2, wr[1], acc1);
        }
    }
    float4 o;
    unpack2(acc0, o.x, o.y);
    unpack2(acc1, o.z, o.w);
    *(float4*)&g_x[(size_t)a * FF + f0] = o;
}

// ---------------------------------------------------------------------------
// 2) Edge radial scalars. R6 inner loop, but ALL memory traffic hoisted to a
//    single staging phase: e tile + all 3 layers' weights loaded once, so the
//    per-layer loop is pure compute + cheap barriers (no phase-locked DRAM
//    stalls across the 3 resident blocks).
//    Dynamic smem layout (bytes):
//      [0)      e_s  : 41*ESTRIDE floats              (43296)
//      [43296)  w1_s : 3*41*21 ull pairs              (20664)
//      [63960)  b1_s : 3*21 ull                       (  504)
//      [64464)  w2_s : 3*42 float                     (  504)
//      [64968)  b2_s : 3 float (pad->64992)
//      [64992)  red  : 256*9 float                    ( 9216)  total 74208
// ---------------------------------------------------------------------------
#define EOF_W1  43296
#define EOF_B1  63960
#define EOF_W2  64464
#define EOF_B2  64968
#define EOF_RED 64992
#define E_SMEM  74208

__global__ __launch_bounds__(NTHRE, 3) void edge_kernel(
    const float* __restrict__ nbr_fea,
    const float* __restrict__ Wr1, const float* __restrict__ br1,
    const float* __restrict__ Wr2, const float* __restrict__ br2)
{
    extern __shared__ char dsm[];
    float* e_s  = (float*)(dsm);
    ull*   w1_s = (ull*)  (dsm + EOF_W1);   // [l][k][pair]
    ull*   b1_s = (ull*)  (dsm + EOF_B1);   // [l][pair]
    float* w2_s = (float*)(dsm + EOF_W2);   // [l][out]
    float* b2_s = (float*)(dsm + EOF_B2);   // [l]
    float* red  = (float*)(dsm + EOF_RED);

    const int t    = threadIdx.x;
    const int og   = t >> 5;            // warp id: pairs og*3 .. og*3+2
    const int lane = t & 31;
    const int p0   = og * 3;
    const int leA  = lane * 4;          // edges leA..leA+3 (contiguous per warp)
    const int leB  = 128 + lane * 4;    // edges leB..leB+3
    const size_t base = (size_t)blockIdx.x * EPB2;

    // ================= single staging phase (all global traffic) ============
    const float* eg_ptr = nbr_fea + base * NBR;
    for (int idx = t; idx < EPB2 * NBR; idx += NTHRE) {
        int le = idx / NBR;
        int k  = idx - le * NBR;
        e_s[k * ESTRIDE + le] = __ldg(&eg_ptr[idx]);
    }
    for (int idx = t; idx < NC * NBR * NPAIRS; idx += NTHRE) {
        int l = idx / (NBR * NPAIRS);
        int r = idx - l * (NBR * NPAIRS);
        int k = r / NPAIRS, j = r - k * NPAIRS;
        int j2 = 2 * j;
        const float* W1l = Wr1 + (size_t)l * NBR * NBR;
        float lo = __ldg(&W1l[k * NBR + j2]);
        float hi = (j2 + 1 < NBR) ? __ldg(&W1l[k * NBR + j2 + 1]) : 0.f;
        w1_s[idx] = pack2(lo, hi);
    }
    if (t < NC * NPAIRS) {
        int l = t / NPAIRS, j = t - l * NPAIRS;
        int j2 = 2 * j;
        float lo = __ldg(&br1[l * NBR + j2]);
        float hi = (j2 + 1 < NBR) ? __ldg(&br1[l * NBR + j2 + 1]) : 0.f;
        b1_s[t] = pack2(lo, hi);
    }
    if (t < NC * 2 * NPAIRS) {
        int l = t / (2 * NPAIRS), j = t - l * (2 * NPAIRS);
        w2_s[t] = (j < NBR) ? __ldg(&Wr2[((size_t)l * NBR + j) * SHH]) : 0.f;
    }
    if (t < NC) b2_s[t] = __ldg(&br2[t * SHH]);
    __syncthreads();

    // ================= layer loop: pure compute =============================
    #pragma unroll 1
    for (int l = 0; l < NC; l++) {
        const ull* w1l = w1_s + l * NBR * NPAIRS;

        // ---- k-loop: acc[edge 0..7][pair 0..2] ----
        ull acc[8][3];
        {
            const ull* b1l = b1_s + l * NPAIRS;
            ull b0 = b1l[p0], b1 = b1l[p0 + 1], b2 = b1l[p0 + 2];
            #pragma unroll
            for (int i = 0; i < 8; i++) { acc[i][0] = b0; acc[i][1] = b1; acc[i][2] = b2; }
        }

        #pragma unroll 2
        for (int k = 0; k < NBR; k++) {
            const float* erow = e_s + k * ESTRIDE;
            float4 a0 = *(const float4*)(erow + leA);   // contiguous 512B / warp
            float4 a1 = *(const float4*)(erow + leB);   // contiguous 512B / warp
            ull bw0 = w1l[k * NPAIRS + p0];
            ull bw1 = w1l[k * NPAIRS + p0 + 1];
            ull bw2 = w1l[k * NPAIRS + p0 + 2];
            float ev[8] = {a0.x, a0.y, a0.z, a0.w, a1.x, a1.y, a1.z, a1.w};
            #pragma unroll
            for (int i = 0; i < 8; i++) {
                ull a2 = pack2(ev[i], ev[i]);
                acc[i][0] = fma2(a2, bw0, acc[i][0]);
                acc[i][1] = fma2(a2, bw1, acc[i][1]);
                acc[i][2] = fma2(a2, bw2, acc[i][2]);
            }
        }

        // ---- epilogue: softplus . w2 partials into red ----
        const float* w2l = w2_s + l * 2 * NPAIRS;
        float w2a = w2l[p0 * 2],     w2b = w2l[p0 * 2 + 1];
        float w2c = w2l[p0 * 2 + 2], w2d = w2l[p0 * 2 + 3];
        float w2e = w2l[p0 * 2 + 4], w2f = w2l[p0 * 2 + 5];
        #pragma unroll
        for (int i = 0; i < 8; i++) {
            float lo, hi, s;
            unpack2(acc[i][0], lo, hi);
            s  = softplusf(lo) * w2a + softplusf(hi) * w2b;
            unpack2(acc[i][1], lo, hi);
            s += softplusf(lo) * w2c + softplusf(hi) * w2d;
            unpack2(acc[i][2], lo, hi);
            s += softplusf(lo) * w2e + softplusf(hi) * w2f;
            int el = (i < 4) ? (leA + i) : (leB + i - 4);
            red[el * 9 + og] = s;
        }
        __syncthreads();

        // ---- cross-warp reduce + store ----
        float b2v = b2_s[l];
        for (int e = t; e < EPB2; e += NTHRE) {
            float s = b2v;
            #pragma unroll
            for (int o = 0; o < NWARPE; o++) s += red[e * 9 + o];
            g_w[(size_t)l * NM + base + e] = s * WSCALE;
        }
        __syncthreads();   // protect red reuse by next layer's epilogue
    }
}

// ---------------------------------------------------------------------------
// 3) Fused conv layer: y = weighted gather of xin, xout = y @ Wtp[l]
//    (exact round-2 code: known-good 124us/layer)
// ---------------------------------------------------------------------------
__global__ __launch_bounds__(256) void conv_kernel(
    const int* __restrict__ nbr_idx, const float* __restrict__ Wtp_l,
    const float* __restrict__ wl,
    const float* __restrict__ xin, float* __restrict__ xout)
{
    __shared__ float y_s[APB][68];
    __shared__ float sW[FF][FF];

    int t = threadIdx.x;
    for (int i = t; i < FF * FF; i += 256) sW[i >> 6][i & 63] = Wtp_l[i];

    int base = blockIdx.x * APB;
    int fg = t & 7;
    int f0 = fg * 8;

    #pragma unroll 1
    for (int r = 0; r < 4; r++) {
        int la = (t >> 3) + r * 32;
        int a  = base + la;
        float4 a0 = make_float4(0.f, 0.f, 0.f, 0.f);
        float4 a1 = make_float4(0.f, 0.f, 0.f, 0.f);
        if (a < NN) {
            #pragma unroll
            for (int j = 0; j < MM; j++) {
                int   s  = __ldg(&nbr_idx[a * MM + j]);
                float wj = __ldg(&wl[a * MM + j]);
                const float4* xr = (const float4*)(xin + (size_t)s * FF + f0);
                float4 v0 = __ldg(&xr[0]);
                float4 v1 = __ldg(&xr[1]);
                a0.x += wj * v0.x; a0.y += wj * v0.y; a0.z += wj * v0.z; a0.w += wj * v0.w;
                a1.x += wj * v1.x; a1.y += wj * v1.y; a1.z += wj * v1.z; a1.w += wj * v1.w;
            }
        }
        *(float4*)&y_s[la][f0]     = a0;
        *(float4*)&y_s[la][f0 + 4] = a1;
    }
    __syncthreads();

    int la0 = (t >> 3) * 4;
    ull acc[4][4];
    #pragma unroll
    for (int i = 0; i < 4; i++)
        #pragma unroll
        for (int p = 0; p < 4; p++) acc[i][p] = 0ULL;

    #pragma unroll 4
    for (int k4 = 0; k4 < FF / 4; k4++) {
        float4 yv[4];
        #pragma unroll
        for (int i = 0; i < 4; i++) yv[i] = *(const float4*)&y_s[la0 + i][k4 * 4];
        #pragma unroll
        for (int c = 0; c < 4; c++) {
            int k = k4 * 4 + c;
            ulonglong2 wa = *(const ulonglong2*)&sW[k][f0];
            ulonglong2 wb = *(const ulonglong2*)&sW[k][f0 + 4];
            #pragma unroll
            for (int i = 0; i < 4; i++) {
                float yc = (c == 0) ? yv[i].x : (c == 1) ? yv[i].y : (c == 2) ? yv[i].z : yv[i].w;
                ull y2 = pack2(yc, yc);
                acc[i][0] = fma2(y2, wa.x, acc[i][0]);
                acc[i][1] = fma2(y2, wa.y, acc[i][1]);
                acc[i][2] = fma2(y2, wb.x, acc[i][2]);
                acc[i][3] = fma2(y2, wb.y, acc[i][3]);
            }
        }
    }

    #pragma unroll
    for (int i = 0; i < 4; i++) {
        int a = base + la0 + i;
        if (a >= NN) break;
        float4 o0, o1;
        unpack2(acc[i][0], o0.x, o0.y);
        unpack2(acc[i][1], o0.z, o0.w);
        unpack2(acc[i][2], o1.x, o1.y);
        unpack2(acc[i][3], o1.z, o1.w);
        float* xo = xout + (size_t)a * FF + f0;
        *(float4*)(xo)     = o0;
        *(float4*)(xo + 4) = o1;
    }
}

// ---------------------------------------------------------------------------
// 4) crystal pooling + fc + out. One block (128 thr) per crystal.
// ---------------------------------------------------------------------------
__global__ __launch_bounds__(128) void pool_kernel(
    const float* __restrict__ xin,
    const int* __restrict__ cidx,
    const float* __restrict__ Wfc, const float* __restrict__ bfc,
    const float* __restrict__ Wout, const float* __restrict__ bout,
    float* __restrict__ out, float* __restrict__ hout)
{
    __shared__ float scrys[FF];
    __shared__ float sred[HF];
    int b    = blockIdx.x;
    int tid  = threadIdx.x;
    int f    = tid & 63;
    int half = tid >> 6;

    float acc = 0.f;
    for (int a = half * (NPB / 2); a < (half + 1) * (NPB / 2); a++) {
        int atom = __ldg(&cidx[b * NPB + a]);
        acc += xin[(size_t)atom * FF + f];
    }
    if (half == 1) scrys[f] = acc;
    __syncthreads();
    if (half == 0) scrys[f] = (scrys[f] + acc) * (1.0f / NPB);
    __syncthreads();

    float hv = bfc[tid];
    #pragma unroll
    for (int k = 0; k < FF; k++) hv += scrys[k] * Wfc[k * HF + tid];
    hv = fmaxf(hv, 0.0f) + log1pf(__expf(-fabsf(hv)));   // precise softplus here
    if (hout) hout[(size_t)b * HF + tid] = hv;

    sred[tid] = hv * Wout[tid];
    __syncthreads();
    #pragma unroll
    for (int s = 64; s > 0; s >>= 1) {
        if (tid < s) sred[tid] += sred[tid + s];
        __syncthreads();
    }
    if (tid == 0) out[b] = sred[0] + bout[0];
}

// ---------------------------------------------------------------------------
extern "C" void kernel_launch(void* const* d_in, const int* in_sizes, int n_in,
                              void* d_out, int out_size)
{
    const float* atom_fea = (const float*)d_in[0];
    const float* nbr_fea  = (const float*)d_in[1];
    const int*   nbr_idx  = (const int*)  d_in[2];
    const int*   cidx     = (const int*)  d_in[3];
    // d_in[4] = pos : unused (Y0 is a constant)
    const float* W_emb = (const float*)d_in[5];
    const float* b_emb = (const float*)d_in[6];
    const float* Wr1   = (const float*)d_in[7];
    const float* br1   = (const float*)d_in[8];
    const float* Wr2   = (const float*)d_in[9];
    const float* br2   = (const float*)d_in[10];
    const float* Wtp   = (const float*)d_in[11];
    const float* W_fc  = (const float*)d_in[12];
    const float* b_fc  = (const float*)d_in[13];
    const float* W_out = (const float*)d_in[14];
    const float* b_out = (const float*)d_in[15];

    float* out_f = (float*)d_out;
    float* h_f   = (out_size >= BB + BB * HF) ? out_f + BB : nullptr;

    float* gx; cudaGetSymbolAddress((void**)&gx, g_x);
    float* gy; cudaGetSymbolAddress((void**)&gy, g_y);
    float* gw; cudaGetSymbolAddress((void**)&gw, g_w);

    static int smem_set = 0;
    if (!smem_set) {
        cudaFuncSetAttribute(edge_kernel,
                             cudaFuncAttributeMaxDynamicSharedMemorySize, E_SMEM);
        smem_set = 1;
    }

    embed_kernel<<<(NN + 15) / 16, 256>>>(atom_fea, W_emb, b_emb);
    edge_kernel<<<NM / EPB2, NTHRE, E_SMEM>>>(nbr_fea, Wr1, br1, Wr2, br2);

    // layer ping-pong: x -> y -> x -> y
    conv_kernel<<<(NN + APB - 1) / APB, 256>>>(nbr_idx, Wtp + 0 * FF * FF, gw + 0 * (size_t)NM, gx, gy);
    conv_kernel<<<(NN + APB - 1) / APB, 256>>>(nbr_idx, Wtp + 1 * FF * FF, gw + 1 * (size_t)NM, gy, gx);
    conv_kernel<<<(NN + APB - 1) / APB, 256>>>(nbr_idx, Wtp + 2 * FF * FF, gw + 2 * (size_t)NM, gx, gy);

    pool_kernel<<<BB, 128>>>(gy, cidx, W_fc, b_fc, W_out, b_out, out_f, h_f);
}